// round 13
// baseline (speedup 1.0000x reference)
#include <cuda_runtime.h>
#include <cuda_fp16.h>

// ---------------- problem constants ----------------
#define BSZ   4
#define NN    512
#define EMBD  64
#define INF   256          // IN_DIM
#define H1    128          // fc1 out (2*HD)
#define HE    64           // e1 out
#define NPAIR (NN*(NN-1))                 // 261632
#define PRED_OFF (BSZ*NN*NN)              // 1048576
#define EMB_OFF  (PRED_OFF + BSZ*NPAIR*2) // 3141632

// ---------------- device scratch (no allocs allowed) ----------------
__device__ float g_emb[BSZ*NN*EMBD];     // emb row-major [b][n][k]
__device__ float g_A  [BSZ*NN*HE];       // emb @ W1top   [b][n][h]
__device__ int   g_cin  = 0;             // grid barrier arrive counter
__device__ int   g_cout = 0;             // grid barrier exit counter (reset)

typedef unsigned int u32;

// smem byte offsets -- stage2 layout
#define EHB   0          // Eh: 512 x 64 fp16, 128B rows, SW128   = 65536
#define UB    65536      // U bufs: 8 x (64 x 64 fp16 = 8192)      = 65536
#define WB    131072     // e1w fp32 (8192 floats)                 = 32768
#define EMBA  163840     // emb_i 16 x 64 f32                      = 4096
#define CCB   167936     // cc 16 x 64 f32                         = 4096
#define WDB   172032     // wd 64 f32                              = 256
#define SM2_TOTAL 172288

// stage1 layout (overlaps the stage2 region, used before the grid barrier)
#define SA_X   0         // X staggered: 4*1048 floats             = 16768 B
#define SA_W   16768     // weights: up to 32768 floats            = 131072 B
#define SA_HS  147840    // Hs: 16*132 floats                      = 8448 B
#define SA_ES  156288    // Es: 16*64 floats                       = 4096 B
// partials P overlay bytes [0, 32768) after a sync

__device__ __forceinline__ u32 hpack(float lo, float hi) {
    __half2 h = __floats2half2_rn(lo, hi);
    return *reinterpret_cast<u32*>(&h);
}

__device__ __forceinline__ void ldsm4(u32& r0, u32& r1, u32& r2, u32& r3, u32 addr) {
    asm volatile("ldmatrix.sync.aligned.m8n8.x4.shared.b16 {%0,%1,%2,%3}, [%4];"
        : "=r"(r0), "=r"(r1), "=r"(r2), "=r"(r3) : "r"(addr));
}
__device__ __forceinline__ void ldsm4t(u32& r0, u32& r1, u32& r2, u32& r3, u32 addr) {
    asm volatile("ldmatrix.sync.aligned.m8n8.x4.trans.shared.b16 {%0,%1,%2,%3}, [%4];"
        : "=r"(r0), "=r"(r1), "=r"(r2), "=r"(r3) : "r"(addr));
}
__device__ __forceinline__ void mma16816(float* d, const u32* a, const u32* b) {
    asm volatile(
        "mma.sync.aligned.m16n8k16.row.col.f32.f16.f16.f32 "
        "{%0,%1,%2,%3}, {%4,%5,%6,%7}, {%8,%9}, {%0,%1,%2,%3};"
        : "+f"(d[0]), "+f"(d[1]), "+f"(d[2]), "+f"(d[3])
        : "r"(a[0]), "r"(a[1]), "r"(a[2]), "r"(a[3]), "r"(b[0]), "r"(b[1]));
}
__device__ __forceinline__ void mma16816_z(float* d, const u32* a, const u32* b) {
    asm volatile(
        "mma.sync.aligned.m16n8k16.row.col.f32.f16.f16.f32 "
        "{%0,%1,%2,%3}, {%4,%5,%6,%7}, {%8,%9}, {%10,%10,%10,%10};"
        : "=f"(d[0]), "=f"(d[1]), "=f"(d[2]), "=f"(d[3])
        : "r"(a[0]), "r"(a[1]), "r"(a[2]), "r"(a[3]), "r"(b[0]), "r"(b[1]),
          "f"(0.f));
}

__device__ __forceinline__ void store_edge(float* __restrict__ out,
                                           int b, int i, int j, float d) {
    float ad  = fabsf(d);
    float ex  = __expf(-ad);
    float inv = 1.f / (1.f + ex);
    float pbig = inv, psml = ex * inv;
    float p1 = d >= 0.f ? pbig : psml;
    float p0 = d >= 0.f ? psml : pbig;
    out[b*NN*NN + i*NN + j] = p1;
    if (j != i) {
        int kidx = i*(NN-1) + (j < i ? j : j - 1);
        reinterpret_cast<float2*>(out + PRED_OFF)[b*NPAIR + kidx] = make_float2(p0, p1);
    }
}

// =====================================================================
// Fused kernel: stage1 (node-reuse k-split MLP) -> grid barrier ->
// stage2 (edge GEMM via mma.sync fp16). Grid 128 x 512, 1 CTA/SM.
// =====================================================================
__global__ __launch_bounds__(512, 1)
void fused(const float* __restrict__ nf,
           const float* __restrict__ fc1w, const float* __restrict__ fc1b,
           const float* __restrict__ fc2w, const float* __restrict__ fc2b,
           const float* __restrict__ e1w,  const float* __restrict__ e1b,
           const float* __restrict__ e2w,  const float* __restrict__ e2b,
           float* __restrict__ out)
{
    extern __shared__ char smc[];
    const u32 sb = (u32)__cvta_generic_to_shared(smc);

    const int t   = threadIdx.x;
    const int bid = blockIdx.x;
    const int nb  = bid * 16;

    float* Xs = reinterpret_cast<float*>(smc + SA_X);
    float* Wf = reinterpret_cast<float*>(smc + SA_W);
    float* Hs = reinterpret_cast<float*>(smc + SA_HS);
    float* Es = reinterpret_cast<float*>(smc + SA_ES);

    // ================= stage 1 =================
    // ---- phase A: h = leaky(X @ fc1 + b1), k-split node-blocked ----
    {
        // stage X in bank-staggered layout Xs[kq*1048 + node*65 + k]
        #pragma unroll
        for (int r = 0; r < 8; r++) {
            int idx = t + r*512;
            int node = idx >> 8, kk = idx & 255;
            Xs[(kk >> 6)*1048 + node*65 + (kk & 63)] = nf[nb*INF + idx];
        }
        // stage ALL of fc1w (32768 floats)
        #pragma unroll
        for (int r = 0; r < 16; r++)
            reinterpret_cast<float4*>(Wf)[t + r*512] =
                reinterpret_cast<const float4*>(fc1w)[t + r*512];
        __syncthreads();

        const int kq = t & 3;            // 64-k chunk
        const int hg = (t >> 2) & 31;    // 4-h group
        const int ng = t >> 7;           // 4-node group

        float acc[4][4];
        #pragma unroll
        for (int n = 0; n < 4; n++)
            #pragma unroll
            for (int h = 0; h < 4; h++) acc[n][h] = 0.f;

        const float* Wk = &Wf[(kq*64)*H1 + hg*4];
        const float* Xk = &Xs[kq*1048 + (ng*4)*65];

        #pragma unroll 16
        for (int k = 0; k < 64; k++) {
            float4 w = *reinterpret_cast<const float4*>(&Wk[k*H1]);
            float x0 = Xk[k], x1 = Xk[65 + k], x2 = Xk[130 + k], x3 = Xk[195 + k];
            acc[0][0] += x0*w.x; acc[0][1] += x0*w.y; acc[0][2] += x0*w.z; acc[0][3] += x0*w.w;
            acc[1][0] += x1*w.x; acc[1][1] += x1*w.y; acc[1][2] += x1*w.z; acc[1][3] += x1*w.w;
            acc[2][0] += x2*w.x; acc[2][1] += x2*w.y; acc[2][2] += x2*w.z; acc[2][3] += x2*w.w;
            acc[3][0] += x3*w.x; acc[3][1] += x3*w.y; acc[3][2] += x3*w.z; acc[3][3] += x3*w.w;
        }
        __syncthreads();   // all X/W reads done; P overlays bytes [0,32768)

        float4* P4 = reinterpret_cast<float4*>(smc);   // [kq][node16][h128/4]
        #pragma unroll
        for (int n = 0; n < 4; n++)
            P4[kq*512 + (ng*4 + n)*32 + hg] =
                make_float4(acc[n][0], acc[n][1], acc[n][2], acc[n][3]);
        __syncthreads();

        // reduce over kq, add bias, leaky -> Hs
        {
            const int node = t >> 5;
            const int h4   = t & 31;
            float4 s0 = P4[0*512 + node*32 + h4];
            float4 s1 = P4[1*512 + node*32 + h4];
            float4 s2 = P4[2*512 + node*32 + h4];
            float4 s3 = P4[3*512 + node*32 + h4];
            float4 bi = reinterpret_cast<const float4*>(fc1b)[h4];
            float v0 = s0.x + s1.x + s2.x + s3.x + bi.x;
            float v1 = s0.y + s1.y + s2.y + s3.y + bi.y;
            float v2 = s0.z + s1.z + s2.z + s3.z + bi.z;
            float v3 = s0.w + s1.w + s2.w + s3.w + bi.w;
            v0 = v0 > 0.f ? v0 : 0.01f*v0;
            v1 = v1 > 0.f ? v1 : 0.01f*v1;
            v2 = v2 > 0.f ? v2 : 0.01f*v2;
            v3 = v3 > 0.f ? v3 : 0.01f*v3;
            Hs[node*132 + h4*4 + 0] = v0;
            Hs[node*132 + h4*4 + 1] = v1;
            Hs[node*132 + h4*4 + 2] = v2;
            Hs[node*132 + h4*4 + 3] = v3;
        }
    }
    __syncthreads();

    // ---- phase B: emb = leaky(h @ fc2 + b2) ----
    #pragma unroll
    for (int r = 0; r < 4; r++)
        reinterpret_cast<float4*>(Wf)[t + r*512] =
            reinterpret_cast<const float4*>(fc2w)[t + r*512];
    __syncthreads();
    {
        const int node = t >> 5;
        const int db   = (t & 31) * 2;
        float b0=0.f, b1=0.f;
        #pragma unroll
        for (int k = 0; k < H1; k++) {
            float hv = Hs[node*132 + k];
            float2 w = *reinterpret_cast<const float2*>(&Wf[k*EMBD + db]);
            b0 += hv*w.x; b1 += hv*w.y;
        }
        float v0 = b0 + fc2b[db+0]; v0 = v0 > 0.f ? v0 : 0.01f*v0;
        float v1 = b1 + fc2b[db+1]; v1 = v1 > 0.f ? v1 : 0.01f*v1;

        Es[node*EMBD + db + 0] = v0;
        Es[node*EMBD + db + 1] = v1;

        const int g = nb + node;
        float2 v2 = make_float2(v0, v1);
        *reinterpret_cast<float2*>(&g_emb[g*EMBD + db]) = v2;
        *reinterpret_cast<float2*>(&out[EMB_OFF + g*EMBD + db]) = v2;
    }
    __syncthreads();

    // ---- phase C: A = emb @ e1_w[:64,:] ----
    #pragma unroll
    for (int r = 0; r < 2; r++)
        reinterpret_cast<float4*>(Wf)[t + r*512] =
            reinterpret_cast<const float4*>(e1w)[t + r*512];
    __syncthreads();
    {
        const int node = t >> 5;
        const int hb2  = (t & 31) * 2;
        float c0=0.f, c1=0.f;
        #pragma unroll
        for (int k = 0; k < EMBD; k++) {
            float ev = Es[node*EMBD + k];
            float2 w = *reinterpret_cast<const float2*>(&Wf[k*HE + hb2]);
            c0 += ev*w.x; c1 += ev*w.y;
        }
        const int g = nb + node;
        *reinterpret_cast<float2*>(&g_A[g*HE + hb2]) = make_float2(c0, c1);
    }

    // ================= grid barrier (128 CTAs co-resident) ===========
    __threadfence();
    __syncthreads();
    if (t == 0) {
        atomicAdd(&g_cin, 1);
        while (atomicAdd(&g_cin, 0) < 128) { }
        __threadfence();
    }
    __syncthreads();

    // ================= stage 2: edge GEMM (unchanged from R11) ==========
    const int lane = t & 31;
    const int wid  = t >> 5;
    const int b     = bid >> 5;
    const int ibase = (bid & 31) * 16;

    float* Wsm  = reinterpret_cast<float*>(smc + WB);
    float* embA = reinterpret_cast<float*>(smc + EMBA);
    float* ccs  = reinterpret_cast<float*>(smc + CCB);
    float* wds  = reinterpret_cast<float*>(smc + WDB);

    #pragma unroll
    for (int r = 0; r < 4; r++)
        reinterpret_cast<float4*>(Wsm)[t + r*512] =
            reinterpret_cast<const float4*>(e1w)[t + r*512];
    if (t < 256)
        reinterpret_cast<float4*>(embA)[t] =
            reinterpret_cast<const float4*>(&g_emb[(b*NN + ibase)*EMBD])[t];
    #pragma unroll
    for (int r = 0; r < 2; r++) {
        int idx = t + r*512, ii = idx >> 6, h = idx & 63;
        ccs[idx] = g_A[(b*NN + ibase + ii)*HE + h] + e1b[h];
    }
    if (t < 64) wds[t] = e2w[t*2 + 1] - e2w[t*2];
    const float bd = e2b[1] - e2b[0];

    {
        const int r = t;
        const float4* src = reinterpret_cast<const float4*>(&g_emb[(b*NN + r)*EMBD]);
        char* ehrow = smc + EHB + r*128;
        const int r7 = r & 7;
        #pragma unroll
        for (int c = 0; c < 8; c++) {
            float4 v0 = src[c*2], v1 = src[c*2 + 1];
            u32 h0 = hpack(v0.x, v0.y), h1 = hpack(v0.z, v0.w);
            u32 h2 = hpack(v1.x, v1.y), h3 = hpack(v1.z, v1.w);
            *reinterpret_cast<uint4*>(ehrow + ((c ^ r7) << 4)) = make_uint4(h0, h1, h2, h3);
        }
    }
    __syncthreads();

    const u32 EhA = sb + EHB;
    const int wj   = wid * 32;
    const int lrow = lane & 15;
    const int lch  = lane >> 4;

    u32 ef[32];
    #pragma unroll
    for (int ks = 0; ks < 4; ks++) {
        #pragma unroll
        for (int jf = 0; jf < 2; jf++) {
            const int ra = wj + jf*16 + lrow;
            const u32 addr = EhA + (u32)(ra*128)
                           + (u32)((((ks*2 + lch) ^ (ra & 7))) << 4);
            u32* e = &ef[(ks*2 + jf)*4];
            ldsm4(e[0], e[1], e[2], e[3], addr);
        }
    }

    u32 boff[8];
    #pragma unroll
    for (int ks = 0; ks < 4; ks++) {
        #pragma unroll
        for (int hh = 0; hh < 2; hh++) {
            const int kr = ks*16 + lrow;
            boff[ks*2 + hh] = (u32)(kr*128 + (((hh*4 + lch) ^ (kr & 7)) << 4));
        }
    }

    auto build_u8 = [&](int phase) {
        const int k = t >> 3;
        const int c = t & 7;
        const float4* w1 = reinterpret_cast<const float4*>(&Wsm[k*64 + c*8]);
        const float4* w2 = reinterpret_cast<const float4*>(&Wsm[4096 + k*64 + c*8]);
        float4 a0 = w1[0], a1 = w1[1];
        float4 b0 = w2[0], b1 = w2[1];
        const u32 co = (u32)((c ^ (k & 7)) << 4);
        #pragma unroll
        for (int q = 0; q < 8; q++) {
            const float e = embA[(phase*8 + q)*64 + k];
            float u0 = fmaf(e, b0.x, -a0.x), u1 = fmaf(e, b0.y, -a0.y);
            float u2 = fmaf(e, b0.z, -a0.z), u3 = fmaf(e, b0.w, -a0.w);
            float u4 = fmaf(e, b1.x, -a1.x), u5 = fmaf(e, b1.y, -a1.y);
            float u6 = fmaf(e, b1.z, -a1.z), u7 = fmaf(e, b1.w, -a1.w);
            u32 p0 = hpack(u0, u1), p1 = hpack(u2, u3);
            u32 p2 = hpack(u4, u5), p3 = hpack(u6, u7);
            char* uh = smc + UB + q*8192 + k*128;
            *reinterpret_cast<uint4*>(uh + co) = make_uint4(p0, p1, p2, p3);
        }
    };

    for (int phase = 0; phase < 2; phase++) {
        build_u8(phase);
        __syncthreads();

        #pragma unroll
        for (int q = 0; q < 8; q++) {
            const int ii = phase*8 + q;
            const u32 Ub = sb + UB + (u32)(q*8192);

            float acc[16][4];

            #pragma unroll
            for (int ks = 0; ks < 4; ks++) {
                #pragma unroll
                for (int hh = 0; hh < 2; hh++) {
                    const u32 a0addr = Ub + boff[ks*2 + hh];
                    u32 bfr[4][2];
                    ldsm4t(bfr[0][0], bfr[0][1], bfr[1][0], bfr[1][1], a0addr);
                    ldsm4t(bfr[2][0], bfr[2][1], bfr[3][0], bfr[3][1], a0addr ^ 32u);
                    #pragma unroll
                    for (int jf = 0; jf < 2; jf++) {
                        const u32* a = &ef[(ks*2 + jf)*4];
                        #pragma unroll
                        for (int h4 = 0; h4 < 4; h4++) {
                            if (ks == 0)
                                mma16816_z(acc[jf*8 + hh*4 + h4], a, bfr[h4]);
                            else
                                mma16816(acc[jf*8 + hh*4 + h4], a, bfr[h4]);
                        }
                    }
                }
            }

            const int t2 = (lane & 3) * 2;
            const int ig2 = ibase + ii;
            float2 ccw[8], wdw[8];
            #pragma unroll
            for (int ht = 0; ht < 8; ht++) {
                ccw[ht] = *reinterpret_cast<const float2*>(&ccs[ii*64 + ht*8 + t2]);
                wdw[ht] = *reinterpret_cast<const float2*>(&wds[ht*8 + t2]);
            }
            float p[4];
            #pragma unroll
            for (int jf = 0; jf < 2; jf++) {
                float s0 = 0.f, s1 = 0.f;
                #pragma unroll
                for (int ht = 0; ht < 8; ht++) {
                    s0 += fmaxf(acc[jf*8+ht][0] + ccw[ht].x, 0.f) * wdw[ht].x
                        + fmaxf(acc[jf*8+ht][1] + ccw[ht].y, 0.f) * wdw[ht].y;
                    s1 += fmaxf(acc[jf*8+ht][2] + ccw[ht].x, 0.f) * wdw[ht].x
                        + fmaxf(acc[jf*8+ht][3] + ccw[ht].y, 0.f) * wdw[ht].y;
                }
                s0 += __shfl_xor_sync(0xffffffffu, s0, 1);
                s0 += __shfl_xor_sync(0xffffffffu, s0, 2);
                s1 += __shfl_xor_sync(0xffffffffu, s1, 1);
                s1 += __shfl_xor_sync(0xffffffffu, s1, 2);
                p[jf*2 + 0] = s0;
                p[jf*2 + 1] = s1;
            }
            const int g   = lane & 7;
            const int src = g * 4;
            float v0 = __shfl_sync(0xffffffffu, p[0], src);
            float v1 = __shfl_sync(0xffffffffu, p[1], src);
            float v2 = __shfl_sync(0xffffffffu, p[2], src);
            float v3 = __shfl_sync(0xffffffffu, p[3], src);
            const int q2 = lane >> 3;
            float d = (q2 == 0) ? v0 : (q2 == 1) ? v1 : (q2 == 2) ? v2 : v3;
            d += bd;
            const int j = wj + ((lane >> 4) << 4) + (((lane >> 3) & 1) << 3) + g;
            store_edge(out, b, ig2, j, d);
        }
        if (phase == 0) __syncthreads();
    }

    // ================= barrier reset (replay-deterministic) ===============
    __syncthreads();
    if (t == 0) {
        int v = atomicAdd(&g_cout, 1);
        if (v == 127) {
            atomicExch(&g_cin, 0);
            atomicExch(&g_cout, 0);
        }
    }
}

// =====================================================================
extern "C" void kernel_launch(void* const* d_in, const int* in_sizes, int n_in,
                              void* d_out, int out_size)
{
    (void)in_sizes; (void)n_in; (void)out_size;
    const float* nf   = (const float*)d_in[0];
    const float* fc1w = (const float*)d_in[1];
    const float* fc1b = (const float*)d_in[2];
    const float* fc2w = (const float*)d_in[3];
    const float* fc2b = (const float*)d_in[4];
    const float* e1w  = (const float*)d_in[5];
    const float* e1b  = (const float*)d_in[6];
    const float* e2w  = (const float*)d_in[7];
    const float* e2b  = (const float*)d_in[8];
    float* out = (float*)d_out;

    cudaFuncSetAttribute(fused, cudaFuncAttributeMaxDynamicSharedMemorySize, SM2_TOTAL);
    fused<<<128, 512, SM2_TOTAL>>>(nf, fc1w, fc1b, fc2w, fc2b,
                                   e1w, e1b, e2w, e2b, out);
}

// round 14
// speedup vs baseline: 1.0732x; 1.0732x over previous
#include <cuda_runtime.h>
#include <cuda_fp16.h>

// ---------------- problem constants ----------------
#define BSZ   4
#define NN    512
#define EMBD  64
#define INF   256          // IN_DIM
#define H1    128          // fc1 out (2*HD)
#define HE    64           // e1 out
#define NPAIR (NN*(NN-1))                 // 261632
#define PRED_OFF (BSZ*NN*NN)              // 1048576
#define EMB_OFF  (PRED_OFF + BSZ*NPAIR*2) // 3141632

// ---------------- device scratch (no allocs allowed) ----------------
__device__ float g_emb[BSZ*NN*EMBD];     // emb row-major [b][n][k]
__device__ float g_A  [BSZ*NN*HE];       // emb @ W1top   [b][n][h]
__device__ int   g_cin  = 0;             // grid barrier arrive counter
__device__ int   g_cout = 0;             // grid barrier exit counter (reset)

typedef unsigned int u32;

// smem byte offsets -- stage2 layout
#define EHB   0          // Eh: 512 x 64 fp16, 128B rows, SW128   = 65536
#define UB    65536      // U bufs: 8 x (64 x 64 fp16 = 8192)      = 65536
#define WB    131072     // e1w fp32 (8192 floats)                 = 32768
#define EMBA  163840     // emb_i 16 x 64 f32                      = 4096
#define CCB   167936     // cc 16 x 64 f32                         = 4096
#define WDB   172032     // wd 64 f32                              = 256
#define SM2_TOTAL 172288

// stage1 layout (overlaps the stage2 region, used before the grid barrier)
#define SA_X   0         // X staggered: 4*1048 floats             = 16768 B
#define SA_W   16768     // weights: up to 32768 floats            = 131072 B
#define SA_HS  147840    // Hs: 16*132 floats                      = 8448 B
#define SA_ES  156288    // Es: 16*64 floats                       = 4096 B

__device__ __forceinline__ u32 hpack(float lo, float hi) {
    __half2 h = __floats2half2_rn(lo, hi);
    return *reinterpret_cast<u32*>(&h);
}

__device__ __forceinline__ void ldsm4(u32& r0, u32& r1, u32& r2, u32& r3, u32 addr) {
    asm volatile("ldmatrix.sync.aligned.m8n8.x4.shared.b16 {%0,%1,%2,%3}, [%4];"
        : "=r"(r0), "=r"(r1), "=r"(r2), "=r"(r3) : "r"(addr));
}
__device__ __forceinline__ void ldsm4t(u32& r0, u32& r1, u32& r2, u32& r3, u32 addr) {
    asm volatile("ldmatrix.sync.aligned.m8n8.x4.trans.shared.b16 {%0,%1,%2,%3}, [%4];"
        : "=r"(r0), "=r"(r1), "=r"(r2), "=r"(r3) : "r"(addr));
}
__device__ __forceinline__ void mma16816(float* d, const u32* a, const u32* b) {
    asm volatile(
        "mma.sync.aligned.m16n8k16.row.col.f32.f16.f16.f32 "
        "{%0,%1,%2,%3}, {%4,%5,%6,%7}, {%8,%9}, {%0,%1,%2,%3};"
        : "+f"(d[0]), "+f"(d[1]), "+f"(d[2]), "+f"(d[3])
        : "r"(a[0]), "r"(a[1]), "r"(a[2]), "r"(a[3]), "r"(b[0]), "r"(b[1]));
}
// first k-step: C = {cc0, cc1, cc0, cc1} (cc depends only on column)
__device__ __forceinline__ void mma16816_c(float* d, const u32* a, const u32* b,
                                           float c0, float c1) {
    asm volatile(
        "mma.sync.aligned.m16n8k16.row.col.f32.f16.f16.f32 "
        "{%0,%1,%2,%3}, {%4,%5,%6,%7}, {%8,%9}, {%10,%11,%10,%11};"
        : "=f"(d[0]), "=f"(d[1]), "=f"(d[2]), "=f"(d[3])
        : "r"(a[0]), "r"(a[1]), "r"(a[2]), "r"(a[3]), "r"(b[0]), "r"(b[1]),
          "f"(c0), "f"(c1));
}

__device__ __forceinline__ void store_edge(float* __restrict__ out,
                                           int b, int i, int j, float d) {
    float ad  = fabsf(d);
    float ex  = __expf(-ad);
    float inv = 1.f / (1.f + ex);
    float pbig = inv, psml = ex * inv;
    float p1 = d >= 0.f ? pbig : psml;
    float p0 = d >= 0.f ? psml : pbig;
    out[b*NN*NN + i*NN + j] = p1;
    if (j != i) {
        int kidx = i*(NN-1) + (j < i ? j : j - 1);
        reinterpret_cast<float2*>(out + PRED_OFF)[b*NPAIR + kidx] = make_float2(p0, p1);
    }
}

// =====================================================================
// Fused kernel: stage1 -> grid barrier (volatile-load spin) -> stage2.
// Grid 128 x 512, 1 CTA/SM, all CTAs co-resident.
// =====================================================================
__global__ __launch_bounds__(512, 1)
void fused(const float* __restrict__ nf,
           const float* __restrict__ fc1w, const float* __restrict__ fc1b,
           const float* __restrict__ fc2w, const float* __restrict__ fc2b,
           const float* __restrict__ e1w,  const float* __restrict__ e1b,
           const float* __restrict__ e2w,  const float* __restrict__ e2b,
           float* __restrict__ out)
{
    extern __shared__ char smc[];
    const u32 sb = (u32)__cvta_generic_to_shared(smc);

    const int t   = threadIdx.x;
    const int bid = blockIdx.x;
    const int nb  = bid * 16;

    float* Xs = reinterpret_cast<float*>(smc + SA_X);
    float* Wf = reinterpret_cast<float*>(smc + SA_W);
    float* Hs = reinterpret_cast<float*>(smc + SA_HS);
    float* Es = reinterpret_cast<float*>(smc + SA_ES);

    // ================= stage 1 =================
    // ---- phase A: h = leaky(X @ fc1 + b1), k-split node-blocked ----
    {
        #pragma unroll
        for (int r = 0; r < 8; r++) {
            int idx = t + r*512;
            int node = idx >> 8, kk = idx & 255;
            Xs[(kk >> 6)*1048 + node*65 + (kk & 63)] = nf[nb*INF + idx];
        }
        #pragma unroll
        for (int r = 0; r < 16; r++)
            reinterpret_cast<float4*>(Wf)[t + r*512] =
                reinterpret_cast<const float4*>(fc1w)[t + r*512];
        __syncthreads();

        const int kq = t & 3;
        const int hg = (t >> 2) & 31;
        const int ng = t >> 7;

        float acc[4][4];
        #pragma unroll
        for (int n = 0; n < 4; n++)
            #pragma unroll
            for (int h = 0; h < 4; h++) acc[n][h] = 0.f;

        const float* Wk = &Wf[(kq*64)*H1 + hg*4];
        const float* Xk = &Xs[kq*1048 + (ng*4)*65];

        #pragma unroll 16
        for (int k = 0; k < 64; k++) {
            float4 w = *reinterpret_cast<const float4*>(&Wk[k*H1]);
            float x0 = Xk[k], x1 = Xk[65 + k], x2 = Xk[130 + k], x3 = Xk[195 + k];
            acc[0][0] += x0*w.x; acc[0][1] += x0*w.y; acc[0][2] += x0*w.z; acc[0][3] += x0*w.w;
            acc[1][0] += x1*w.x; acc[1][1] += x1*w.y; acc[1][2] += x1*w.z; acc[1][3] += x1*w.w;
            acc[2][0] += x2*w.x; acc[2][1] += x2*w.y; acc[2][2] += x2*w.z; acc[2][3] += x2*w.w;
            acc[3][0] += x3*w.x; acc[3][1] += x3*w.y; acc[3][2] += x3*w.z; acc[3][3] += x3*w.w;
        }
        __syncthreads();

        float4* P4 = reinterpret_cast<float4*>(smc);   // [kq][node16][h128/4]
        #pragma unroll
        for (int n = 0; n < 4; n++)
            P4[kq*512 + (ng*4 + n)*32 + hg] =
                make_float4(acc[n][0], acc[n][1], acc[n][2], acc[n][3]);
        __syncthreads();

        {
            const int node = t >> 5;
            const int h4   = t & 31;
            float4 s0 = P4[0*512 + node*32 + h4];
            float4 s1 = P4[1*512 + node*32 + h4];
            float4 s2 = P4[2*512 + node*32 + h4];
            float4 s3 = P4[3*512 + node*32 + h4];
            float4 bi = reinterpret_cast<const float4*>(fc1b)[h4];
            float v0 = s0.x + s1.x + s2.x + s3.x + bi.x;
            float v1 = s0.y + s1.y + s2.y + s3.y + bi.y;
            float v2 = s0.z + s1.z + s2.z + s3.z + bi.z;
            float v3 = s0.w + s1.w + s2.w + s3.w + bi.w;
            v0 = v0 > 0.f ? v0 : 0.01f*v0;
            v1 = v1 > 0.f ? v1 : 0.01f*v1;
            v2 = v2 > 0.f ? v2 : 0.01f*v2;
            v3 = v3 > 0.f ? v3 : 0.01f*v3;
            Hs[node*132 + h4*4 + 0] = v0;
            Hs[node*132 + h4*4 + 1] = v1;
            Hs[node*132 + h4*4 + 2] = v2;
            Hs[node*132 + h4*4 + 3] = v3;
        }
    }
    __syncthreads();

    // ---- phase B: emb = leaky(h @ fc2 + b2) ----
    #pragma unroll
    for (int r = 0; r < 4; r++)
        reinterpret_cast<float4*>(Wf)[t + r*512] =
            reinterpret_cast<const float4*>(fc2w)[t + r*512];
    __syncthreads();
    {
        const int node = t >> 5;
        const int db   = (t & 31) * 2;
        float b0=0.f, b1=0.f;
        #pragma unroll
        for (int k = 0; k < H1; k++) {
            float hv = Hs[node*132 + k];
            float2 w = *reinterpret_cast<const float2*>(&Wf[k*EMBD + db]);
            b0 += hv*w.x; b1 += hv*w.y;
        }
        float v0 = b0 + fc2b[db+0]; v0 = v0 > 0.f ? v0 : 0.01f*v0;
        float v1 = b1 + fc2b[db+1]; v1 = v1 > 0.f ? v1 : 0.01f*v1;

        Es[node*EMBD + db + 0] = v0;
        Es[node*EMBD + db + 1] = v1;

        const int g = nb + node;
        float2 v2 = make_float2(v0, v1);
        *reinterpret_cast<float2*>(&g_emb[g*EMBD + db]) = v2;
        *reinterpret_cast<float2*>(&out[EMB_OFF + g*EMBD + db]) = v2;
    }
    __syncthreads();

    // ---- phase C: A = emb @ e1_w[:64,:] ----
    #pragma unroll
    for (int r = 0; r < 2; r++)
        reinterpret_cast<float4*>(Wf)[t + r*512] =
            reinterpret_cast<const float4*>(e1w)[t + r*512];
    __syncthreads();
    {
        const int node = t >> 5;
        const int hb2  = (t & 31) * 2;
        float c0=0.f, c1=0.f;
        #pragma unroll
        for (int k = 0; k < EMBD; k++) {
            float ev = Es[node*EMBD + k];
            float2 w = *reinterpret_cast<const float2*>(&Wf[k*HE + hb2]);
            c0 += ev*w.x; c1 += ev*w.y;
        }
        const int g = nb + node;
        *reinterpret_cast<float2*>(&g_A[g*HE + hb2]) = make_float2(c0, c1);
    }

    // ====== grid barrier: atomic arrive, VOLATILE-LOAD poll ==============
    __threadfence();
    __syncthreads();
    if (t == 0) {
        atomicAdd(&g_cin, 1);
        volatile int* p = &g_cin;
        while (*p < 128) { }
        __threadfence();
    }
    __syncthreads();

    // ================= stage 2: edge GEMM ================================
    const int lane = t & 31;
    const int wid  = t >> 5;
    const int b     = bid >> 5;
    const int ibase = (bid & 31) * 16;

    float* Wsm  = reinterpret_cast<float*>(smc + WB);
    float* embA = reinterpret_cast<float*>(smc + EMBA);
    float* ccs  = reinterpret_cast<float*>(smc + CCB);
    float* wds  = reinterpret_cast<float*>(smc + WDB);

    #pragma unroll
    for (int r = 0; r < 4; r++)
        reinterpret_cast<float4*>(Wsm)[t + r*512] =
            reinterpret_cast<const float4*>(e1w)[t + r*512];
    if (t < 256)
        reinterpret_cast<float4*>(embA)[t] =
            reinterpret_cast<const float4*>(&g_emb[(b*NN + ibase)*EMBD])[t];
    #pragma unroll
    for (int r = 0; r < 2; r++) {
        int idx = t + r*512, ii = idx >> 6, h = idx & 63;
        ccs[idx] = g_A[(b*NN + ibase + ii)*HE + h] + e1b[h];
    }
    if (t < 64) wds[t] = e2w[t*2 + 1] - e2w[t*2];
    const float bd = e2b[1] - e2b[0];

    {
        const int r = t;
        const float4* src = reinterpret_cast<const float4*>(&g_emb[(b*NN + r)*EMBD]);
        char* ehrow = smc + EHB + r*128;
        const int r7 = r & 7;
        #pragma unroll
        for (int c = 0; c < 8; c++) {
            float4 v0 = src[c*2], v1 = src[c*2 + 1];
            u32 h0 = hpack(v0.x, v0.y), h1 = hpack(v0.z, v0.w);
            u32 h2 = hpack(v1.x, v1.y), h3 = hpack(v1.z, v1.w);
            *reinterpret_cast<uint4*>(ehrow + ((c ^ r7) << 4)) = make_uint4(h0, h1, h2, h3);
        }
    }
    __syncthreads();

    const u32 EhA = sb + EHB;
    const int wj   = wid * 32;
    const int lrow = lane & 15;
    const int lch  = lane >> 4;

    // preload E A-fragments: 32j x 64k = 8 x ldsm4
    u32 ef[32];
    #pragma unroll
    for (int ks = 0; ks < 4; ks++) {
        #pragma unroll
        for (int jf = 0; jf < 2; jf++) {
            const int ra = wj + jf*16 + lrow;
            const u32 addr = EhA + (u32)(ra*128)
                           + (u32)((((ks*2 + lch) ^ (ra & 7))) << 4);
            u32* e = &ef[(ks*2 + jf)*4];
            ldsm4(e[0], e[1], e[2], e[3], addr);
        }
    }

    // hoisted B-frag swizzled offsets: [ks][hh], nb=0
    u32 boff[8];
    #pragma unroll
    for (int ks = 0; ks < 4; ks++) {
        #pragma unroll
        for (int hh = 0; hh < 2; hh++) {
            const int kr = ks*16 + lrow;
            boff[ks*2 + hh] = (u32)(kr*128 + (((hh*4 + lch) ^ (kr & 7)) << 4));
        }
    }

    auto build_u8 = [&](int phase) {
        const int k = t >> 3;
        const int c = t & 7;
        const float4* w1 = reinterpret_cast<const float4*>(&Wsm[k*64 + c*8]);
        const float4* w2 = reinterpret_cast<const float4*>(&Wsm[4096 + k*64 + c*8]);
        float4 a0 = w1[0], a1 = w1[1];
        float4 b0 = w2[0], b1 = w2[1];
        const u32 co = (u32)((c ^ (k & 7)) << 4);
        #pragma unroll
        for (int q = 0; q < 8; q++) {
            const float e = embA[(phase*8 + q)*64 + k];
            float u0 = fmaf(e, b0.x, -a0.x), u1 = fmaf(e, b0.y, -a0.y);
            float u2 = fmaf(e, b0.z, -a0.z), u3 = fmaf(e, b0.w, -a0.w);
            float u4 = fmaf(e, b1.x, -a1.x), u5 = fmaf(e, b1.y, -a1.y);
            float u6 = fmaf(e, b1.z, -a1.z), u7 = fmaf(e, b1.w, -a1.w);
            u32 p0 = hpack(u0, u1), p1 = hpack(u2, u3);
            u32 p2 = hpack(u4, u5), p3 = hpack(u6, u7);
            char* uh = smc + UB + q*8192 + k*128;
            *reinterpret_cast<uint4*>(uh + co) = make_uint4(p0, p1, p2, p3);
        }
    };

    const int t2 = (lane & 3) * 2;

    for (int phase = 0; phase < 2; phase++) {
        build_u8(phase);
        __syncthreads();

        #pragma unroll
        for (int q = 0; q < 8; q++) {
            const int ii = phase*8 + q;
            const u32 Ub = sb + UB + (u32)(q*8192);
            const float2* ccp = reinterpret_cast<const float2*>(&ccs[ii*64 + t2]);

            float acc[16][4];

            #pragma unroll
            for (int ks = 0; ks < 4; ks++) {
                #pragma unroll
                for (int hh = 0; hh < 2; hh++) {
                    const u32 a0addr = Ub + boff[ks*2 + hh];
                    u32 bfr[4][2];
                    ldsm4t(bfr[0][0], bfr[0][1], bfr[1][0], bfr[1][1], a0addr);
                    ldsm4t(bfr[2][0], bfr[2][1], bfr[3][0], bfr[3][1], a0addr ^ 32u);
                    #pragma unroll
                    for (int jf = 0; jf < 2; jf++) {
                        const u32* a = &ef[(ks*2 + jf)*4];
                        #pragma unroll
                        for (int h4 = 0; h4 < 4; h4++) {
                            if (ks == 0) {
                                // fold cc into the C operand of the first mma
                                float2 cw = ccp[(hh*4 + h4) * 4];   // stride 8 floats
                                mma16816_c(acc[jf*8 + hh*4 + h4], a, bfr[h4],
                                           cw.x, cw.y);
                            } else {
                                mma16816(acc[jf*8 + hh*4 + h4], a, bfr[h4]);
                            }
                        }
                    }
                }
            }

            // ---- epilogue: relu*wd dot, quad reduce, 32-lane distribute ----
            const int ig2 = ibase + ii;
            float2 wdw[8];
            #pragma unroll
            for (int ht = 0; ht < 8; ht++)
                wdw[ht] = *reinterpret_cast<const float2*>(&wds[ht*8 + t2]);
            float p[4];
            #pragma unroll
            for (int jf = 0; jf < 2; jf++) {
                float s0 = 0.f, s1 = 0.f;
                #pragma unroll
                for (int ht = 0; ht < 8; ht++) {
                    s0 += fmaxf(acc[jf*8+ht][0], 0.f) * wdw[ht].x
                        + fmaxf(acc[jf*8+ht][1], 0.f) * wdw[ht].y;
                    s1 += fmaxf(acc[jf*8+ht][2], 0.f) * wdw[ht].x
                        + fmaxf(acc[jf*8+ht][3], 0.f) * wdw[ht].y;
                }
                s0 += __shfl_xor_sync(0xffffffffu, s0, 1);
                s0 += __shfl_xor_sync(0xffffffffu, s0, 2);
                s1 += __shfl_xor_sync(0xffffffffu, s1, 1);
                s1 += __shfl_xor_sync(0xffffffffu, s1, 2);
                p[jf*2 + 0] = s0;
                p[jf*2 + 1] = s1;
            }
            const int g   = lane & 7;
            const int src = g * 4;
            float v0 = __shfl_sync(0xffffffffu, p[0], src);
            float v1 = __shfl_sync(0xffffffffu, p[1], src);
            float v2 = __shfl_sync(0xffffffffu, p[2], src);
            float v3 = __shfl_sync(0xffffffffu, p[3], src);
            const int q2 = lane >> 3;
            float d = (q2 == 0) ? v0 : (q2 == 1) ? v1 : (q2 == 2) ? v2 : v3;
            d += bd;
            const int j = wj + ((lane >> 4) << 4) + (((lane >> 3) & 1) << 3) + g;
            store_edge(out, b, ig2, j, d);
        }
        if (phase == 0) __syncthreads();
    }

    // ================= barrier reset (replay-deterministic) ===============
    __syncthreads();
    if (t == 0) {
        int v = atomicAdd(&g_cout, 1);
        if (v == 127) {
            atomicExch(&g_cin, 0);
            atomicExch(&g_cout, 0);
        }
    }
}

// =====================================================================
extern "C" void kernel_launch(void* const* d_in, const int* in_sizes, int n_in,
                              void* d_out, int out_size)
{
    (void)in_sizes; (void)n_in; (void)out_size;
    const float* nf   = (const float*)d_in[0];
    const float* fc1w = (const float*)d_in[1];
    const float* fc1b = (const float*)d_in[2];
    const float* fc2w = (const float*)d_in[3];
    const float* fc2b = (const float*)d_in[4];
    const float* e1w  = (const float*)d_in[5];
    const float* e1b  = (const float*)d_in[6];
    const float* e2w  = (const float*)d_in[7];
    const float* e2b  = (const float*)d_in[8];
    float* out = (float*)d_out;

    cudaFuncSetAttribute(fused, cudaFuncAttributeMaxDynamicSharedMemorySize, SM2_TOTAL);
    fused<<<128, 512, SM2_TOTAL>>>(nf, fc1w, fc1b, fc2w, fc2b,
                                   e1w, e1b, e2w, e2b, out);
}

// round 15
// speedup vs baseline: 1.0786x; 1.0050x over previous
#include <cuda_runtime.h>
#include <cuda_fp16.h>

// ---------------- problem constants ----------------
#define BSZ   4
#define NN    512
#define EMBD  64
#define INF   256          // IN_DIM
#define H1    128          // fc1 out (2*HD)
#define HE    64           // e1 out
#define NPAIR (NN*(NN-1))                 // 261632
#define PRED_OFF (BSZ*NN*NN)              // 1048576
#define EMB_OFF  (PRED_OFF + BSZ*NPAIR*2) // 3141632

// ---------------- device scratch (no allocs allowed) ----------------
__device__ float g_emb[BSZ*NN*EMBD];     // emb row-major [b][n][k]
__device__ float g_A  [BSZ*NN*HE];       // emb @ W1top   [b][n][h]
__device__ int   g_cin  = 0;             // grid barrier arrive counter
__device__ int   g_cout = 0;             // grid barrier exit counter (reset)

typedef unsigned int u32;

// smem byte offsets -- stage2 layout
#define EHB   0          // Eh: 512 x 64 fp16, 128B rows, SW128   = 65536
#define UB    65536      // U bufs: 8 x (64 x 64 fp16 = 8192)      = 65536
#define WB    131072     // e1w fp32 (8192 floats)                 = 32768
#define EMBA  163840     // emb_i 16 x 64 f32                      = 4096
#define CCB   167936     // cc 16 x 64 f32                         = 4096
#define WDB   172032     // wd 64 f32                              = 256
#define SM2_TOTAL 172288

// stage1 layout (overlaps the stage2 region, used before the grid barrier)
#define SA_X   0         // X staggered: 4*1048 floats             = 16768 B
#define SA_W   16768     // weights: up to 32768 floats            = 131072 B
#define SA_HS  147840    // Hs: 16*132 floats                      = 8448 B
#define SA_ES  156288    // Es: 16*64 floats                       = 4096 B

__device__ __forceinline__ u32 hpack(float lo, float hi) {
    __half2 h = __floats2half2_rn(lo, hi);
    return *reinterpret_cast<u32*>(&h);
}

__device__ __forceinline__ void ldsm4(u32& r0, u32& r1, u32& r2, u32& r3, u32 addr) {
    asm volatile("ldmatrix.sync.aligned.m8n8.x4.shared.b16 {%0,%1,%2,%3}, [%4];"
        : "=r"(r0), "=r"(r1), "=r"(r2), "=r"(r3) : "r"(addr));
}
__device__ __forceinline__ void ldsm4t(u32& r0, u32& r1, u32& r2, u32& r3, u32 addr) {
    asm volatile("ldmatrix.sync.aligned.m8n8.x4.trans.shared.b16 {%0,%1,%2,%3}, [%4];"
        : "=r"(r0), "=r"(r1), "=r"(r2), "=r"(r3) : "r"(addr));
}
__device__ __forceinline__ void mma16816(float* d, const u32* a, const u32* b) {
    asm volatile(
        "mma.sync.aligned.m16n8k16.row.col.f32.f16.f16.f32 "
        "{%0,%1,%2,%3}, {%4,%5,%6,%7}, {%8,%9}, {%0,%1,%2,%3};"
        : "+f"(d[0]), "+f"(d[1]), "+f"(d[2]), "+f"(d[3])
        : "r"(a[0]), "r"(a[1]), "r"(a[2]), "r"(a[3]), "r"(b[0]), "r"(b[1]));
}
// first k-step: C = {cc0, cc1, cc0, cc1} (cc depends only on column)
__device__ __forceinline__ void mma16816_c(float* d, const u32* a, const u32* b,
                                           float c0, float c1) {
    asm volatile(
        "mma.sync.aligned.m16n8k16.row.col.f32.f16.f16.f32 "
        "{%0,%1,%2,%3}, {%4,%5,%6,%7}, {%8,%9}, {%10,%11,%10,%11};"
        : "=f"(d[0]), "=f"(d[1]), "=f"(d[2]), "=f"(d[3])
        : "r"(a[0]), "r"(a[1]), "r"(a[2]), "r"(a[3]), "r"(b[0]), "r"(b[1]),
          "f"(c0), "f"(c1));
}

__device__ __forceinline__ void store_edge(float* __restrict__ out,
                                           int b, int i, int j, float d) {
    float ad  = fabsf(d);
    float ex  = __expf(-ad);
    float inv = 1.f / (1.f + ex);
    float pbig = inv, psml = ex * inv;
    float p1 = d >= 0.f ? pbig : psml;
    float p0 = d >= 0.f ? psml : pbig;
    out[b*NN*NN + i*NN + j] = p1;
    if (j != i) {
        int kidx = i*(NN-1) + (j < i ? j : j - 1);
        reinterpret_cast<float2*>(out + PRED_OFF)[b*NPAIR + kidx] = make_float2(p0, p1);
    }
}

// =====================================================================
// Fused kernel: stage1 -> grid barrier (volatile-load spin) -> stage2.
// Grid 128 x 512, 1 CTA/SM, all CTAs co-resident.
// =====================================================================
__global__ __launch_bounds__(512, 1)
void fused(const float* __restrict__ nf,
           const float* __restrict__ fc1w, const float* __restrict__ fc1b,
           const float* __restrict__ fc2w, const float* __restrict__ fc2b,
           const float* __restrict__ e1w,  const float* __restrict__ e1b,
           const float* __restrict__ e2w,  const float* __restrict__ e2b,
           float* __restrict__ out)
{
    extern __shared__ char smc[];
    const u32 sb = (u32)__cvta_generic_to_shared(smc);

    const int t   = threadIdx.x;
    const int bid = blockIdx.x;
    const int nb  = bid * 16;

    float* Xs = reinterpret_cast<float*>(smc + SA_X);
    float* Wf = reinterpret_cast<float*>(smc + SA_W);
    float* Hs = reinterpret_cast<float*>(smc + SA_HS);
    float* Es = reinterpret_cast<float*>(smc + SA_ES);

    // ================= stage 1 =================
    // ---- phase A: h = leaky(X @ fc1 + b1), k-split node-blocked ----
    {
        #pragma unroll
        for (int r = 0; r < 8; r++) {
            int idx = t + r*512;
            int node = idx >> 8, kk = idx & 255;
            Xs[(kk >> 6)*1048 + node*65 + (kk & 63)] = nf[nb*INF + idx];
        }
        #pragma unroll
        for (int r = 0; r < 16; r++)
            reinterpret_cast<float4*>(Wf)[t + r*512] =
                reinterpret_cast<const float4*>(fc1w)[t + r*512];
        __syncthreads();

        const int kq = t & 3;
        const int hg = (t >> 2) & 31;
        const int ng = t >> 7;

        float acc[4][4];
        #pragma unroll
        for (int n = 0; n < 4; n++)
            #pragma unroll
            for (int h = 0; h < 4; h++) acc[n][h] = 0.f;

        const float* Wk = &Wf[(kq*64)*H1 + hg*4];
        const float* Xk = &Xs[kq*1048 + (ng*4)*65];

        #pragma unroll 16
        for (int k = 0; k < 64; k++) {
            float4 w = *reinterpret_cast<const float4*>(&Wk[k*H1]);
            float x0 = Xk[k], x1 = Xk[65 + k], x2 = Xk[130 + k], x3 = Xk[195 + k];
            acc[0][0] += x0*w.x; acc[0][1] += x0*w.y; acc[0][2] += x0*w.z; acc[0][3] += x0*w.w;
            acc[1][0] += x1*w.x; acc[1][1] += x1*w.y; acc[1][2] += x1*w.z; acc[1][3] += x1*w.w;
            acc[2][0] += x2*w.x; acc[2][1] += x2*w.y; acc[2][2] += x2*w.z; acc[2][3] += x2*w.w;
            acc[3][0] += x3*w.x; acc[3][1] += x3*w.y; acc[3][2] += x3*w.z; acc[3][3] += x3*w.w;
        }
        __syncthreads();

        float4* P4 = reinterpret_cast<float4*>(smc);   // [kq][node16][h128/4]
        #pragma unroll
        for (int n = 0; n < 4; n++)
            P4[kq*512 + (ng*4 + n)*32 + hg] =
                make_float4(acc[n][0], acc[n][1], acc[n][2], acc[n][3]);
        __syncthreads();

        {
            const int node = t >> 5;
            const int h4   = t & 31;
            float4 s0 = P4[0*512 + node*32 + h4];
            float4 s1 = P4[1*512 + node*32 + h4];
            float4 s2 = P4[2*512 + node*32 + h4];
            float4 s3 = P4[3*512 + node*32 + h4];
            float4 bi = reinterpret_cast<const float4*>(fc1b)[h4];
            float v0 = (s0.x + s1.x) + (s2.x + s3.x) + bi.x;
            float v1 = (s0.y + s1.y) + (s2.y + s3.y) + bi.y;
            float v2 = (s0.z + s1.z) + (s2.z + s3.z) + bi.z;
            float v3 = (s0.w + s1.w) + (s2.w + s3.w) + bi.w;
            v0 = v0 > 0.f ? v0 : 0.01f*v0;
            v1 = v1 > 0.f ? v1 : 0.01f*v1;
            v2 = v2 > 0.f ? v2 : 0.01f*v2;
            v3 = v3 > 0.f ? v3 : 0.01f*v3;
            Hs[node*132 + h4*4 + 0] = v0;
            Hs[node*132 + h4*4 + 1] = v1;
            Hs[node*132 + h4*4 + 2] = v2;
            Hs[node*132 + h4*4 + 3] = v3;
        }
    }
    __syncthreads();

    // ---- phase B: emb = leaky(h @ fc2 + b2), 2-way split k-chains ----
    #pragma unroll
    for (int r = 0; r < 4; r++)
        reinterpret_cast<float4*>(Wf)[t + r*512] =
            reinterpret_cast<const float4*>(fc2w)[t + r*512];
    __syncthreads();
    {
        const int node = t >> 5;
        const int db   = (t & 31) * 2;
        float b0a=0.f, b1a=0.f, b0b=0.f, b1b=0.f;
        #pragma unroll
        for (int k = 0; k < 64; k++) {
            float hv0 = Hs[node*132 + k];
            float hv1 = Hs[node*132 + 64 + k];
            float2 w0 = *reinterpret_cast<const float2*>(&Wf[k*EMBD + db]);
            float2 w1 = *reinterpret_cast<const float2*>(&Wf[(64 + k)*EMBD + db]);
            b0a += hv0*w0.x; b1a += hv0*w0.y;
            b0b += hv1*w1.x; b1b += hv1*w1.y;
        }
        float v0 = (b0a + b0b) + fc2b[db+0]; v0 = v0 > 0.f ? v0 : 0.01f*v0;
        float v1 = (b1a + b1b) + fc2b[db+1]; v1 = v1 > 0.f ? v1 : 0.01f*v1;

        Es[node*EMBD + db + 0] = v0;
        Es[node*EMBD + db + 1] = v1;

        const int g = nb + node;
        float2 v2 = make_float2(v0, v1);
        *reinterpret_cast<float2*>(&g_emb[g*EMBD + db]) = v2;
        *reinterpret_cast<float2*>(&out[EMB_OFF + g*EMBD + db]) = v2;
    }
    __syncthreads();

    // ---- phase C: A = emb @ e1_w[:64,:], 2-way split k-chains ----
    #pragma unroll
    for (int r = 0; r < 2; r++)
        reinterpret_cast<float4*>(Wf)[t + r*512] =
            reinterpret_cast<const float4*>(e1w)[t + r*512];
    __syncthreads();
    {
        const int node = t >> 5;
        const int hb2  = (t & 31) * 2;
        float c0a=0.f, c1a=0.f, c0b=0.f, c1b=0.f;
        #pragma unroll
        for (int k = 0; k < 32; k++) {
            float ev0 = Es[node*EMBD + k];
            float ev1 = Es[node*EMBD + 32 + k];
            float2 w0 = *reinterpret_cast<const float2*>(&Wf[k*HE + hb2]);
            float2 w1 = *reinterpret_cast<const float2*>(&Wf[(32 + k)*HE + hb2]);
            c0a += ev0*w0.x; c1a += ev0*w0.y;
            c0b += ev1*w1.x; c1b += ev1*w1.y;
        }
        const int g = nb + node;
        *reinterpret_cast<float2*>(&g_A[g*HE + hb2]) =
            make_float2(c0a + c0b, c1a + c1b);
    }

    // ====== grid barrier: atomic arrive, volatile-load poll ==============
    __threadfence();
    __syncthreads();
    if (t == 0) {
        atomicAdd(&g_cin, 1);
        volatile int* p = &g_cin;
        while (*p < 128) { }
        __threadfence();
    }
    __syncthreads();

    // ================= stage 2: edge GEMM ================================
    const int lane = t & 31;
    const int wid  = t >> 5;
    const int b     = bid >> 5;
    const int ibase = (bid & 31) * 16;

    float* Wsm  = reinterpret_cast<float*>(smc + WB);
    float* embA = reinterpret_cast<float*>(smc + EMBA);
    float* ccs  = reinterpret_cast<float*>(smc + CCB);
    float* wds  = reinterpret_cast<float*>(smc + WDB);

    #pragma unroll
    for (int r = 0; r < 4; r++)
        reinterpret_cast<float4*>(Wsm)[t + r*512] =
            reinterpret_cast<const float4*>(e1w)[t + r*512];
    if (t < 256)
        reinterpret_cast<float4*>(embA)[t] =
            reinterpret_cast<const float4*>(&g_emb[(b*NN + ibase)*EMBD])[t];
    #pragma unroll
    for (int r = 0; r < 2; r++) {
        int idx = t + r*512, ii = idx >> 6, h = idx & 63;
        ccs[idx] = g_A[(b*NN + ibase + ii)*HE + h] + e1b[h];
    }
    if (t < 64) wds[t] = e2w[t*2 + 1] - e2w[t*2];
    const float bd = e2b[1] - e2b[0];

    {
        const int r = t;
        const float4* src = reinterpret_cast<const float4*>(&g_emb[(b*NN + r)*EMBD]);
        char* ehrow = smc + EHB + r*128;
        const int r7 = r & 7;
        #pragma unroll
        for (int c = 0; c < 8; c++) {
            float4 v0 = src[c*2], v1 = src[c*2 + 1];
            u32 h0 = hpack(v0.x, v0.y), h1 = hpack(v0.z, v0.w);
            u32 h2 = hpack(v1.x, v1.y), h3 = hpack(v1.z, v1.w);
            *reinterpret_cast<uint4*>(ehrow + ((c ^ r7) << 4)) = make_uint4(h0, h1, h2, h3);
        }
    }
    __syncthreads();

    const u32 EhA = sb + EHB;
    const int wj   = wid * 32;
    const int lrow = lane & 15;
    const int lch  = lane >> 4;

    // preload E A-fragments: 32j x 64k = 8 x ldsm4
    u32 ef[32];
    #pragma unroll
    for (int ks = 0; ks < 4; ks++) {
        #pragma unroll
        for (int jf = 0; jf < 2; jf++) {
            const int ra = wj + jf*16 + lrow;
            const u32 addr = EhA + (u32)(ra*128)
                           + (u32)((((ks*2 + lch) ^ (ra & 7))) << 4);
            u32* e = &ef[(ks*2 + jf)*4];
            ldsm4(e[0], e[1], e[2], e[3], addr);
        }
    }

    // hoisted B-frag swizzled offsets: [ks][hh], nb=0
    u32 boff[8];
    #pragma unroll
    for (int ks = 0; ks < 4; ks++) {
        #pragma unroll
        for (int hh = 0; hh < 2; hh++) {
            const int kr = ks*16 + lrow;
            boff[ks*2 + hh] = (u32)(kr*128 + (((hh*4 + lch) ^ (kr & 7)) << 4));
        }
    }

    auto build_u8 = [&](int phase) {
        const int k = t >> 3;
        const int c = t & 7;
        const float4* w1 = reinterpret_cast<const float4*>(&Wsm[k*64 + c*8]);
        const float4* w2 = reinterpret_cast<const float4*>(&Wsm[4096 + k*64 + c*8]);
        float4 a0 = w1[0], a1 = w1[1];
        float4 b0 = w2[0], b1 = w2[1];
        const u32 co = (u32)((c ^ (k & 7)) << 4);
        #pragma unroll
        for (int q = 0; q < 8; q++) {
            const float e = embA[(phase*8 + q)*64 + k];
            float u0 = fmaf(e, b0.x, -a0.x), u1 = fmaf(e, b0.y, -a0.y);
            float u2 = fmaf(e, b0.z, -a0.z), u3 = fmaf(e, b0.w, -a0.w);
            float u4 = fmaf(e, b1.x, -a1.x), u5 = fmaf(e, b1.y, -a1.y);
            float u6 = fmaf(e, b1.z, -a1.z), u7 = fmaf(e, b1.w, -a1.w);
            u32 p0 = hpack(u0, u1), p1 = hpack(u2, u3);
            u32 p2 = hpack(u4, u5), p3 = hpack(u6, u7);
            char* uh = smc + UB + q*8192 + k*128;
            *reinterpret_cast<uint4*>(uh + co) = make_uint4(p0, p1, p2, p3);
        }
    };

    const int t2 = (lane & 3) * 2;

    for (int phase = 0; phase < 2; phase++) {
        build_u8(phase);
        __syncthreads();

        #pragma unroll
        for (int qi = 0; qi < 8; qi++) {
            // stagger: each warp walks the 8 U buffers in a rotated order
            const int q  = (qi + wid) & 7;
            const int ii = phase*8 + q;
            const u32 Ub = sb + UB + (u32)(q*8192);
            const float2* ccp = reinterpret_cast<const float2*>(&ccs[ii*64 + t2]);

            float acc[16][4];

            #pragma unroll
            for (int ks = 0; ks < 4; ks++) {
                #pragma unroll
                for (int hh = 0; hh < 2; hh++) {
                    const u32 a0addr = Ub + boff[ks*2 + hh];
                    u32 bfr[4][2];
                    ldsm4t(bfr[0][0], bfr[0][1], bfr[1][0], bfr[1][1], a0addr);
                    ldsm4t(bfr[2][0], bfr[2][1], bfr[3][0], bfr[3][1], a0addr ^ 32u);
                    #pragma unroll
                    for (int jf = 0; jf < 2; jf++) {
                        const u32* a = &ef[(ks*2 + jf)*4];
                        #pragma unroll
                        for (int h4 = 0; h4 < 4; h4++) {
                            if (ks == 0) {
                                float2 cw = ccp[(hh*4 + h4) * 4];   // stride 8 floats
                                mma16816_c(acc[jf*8 + hh*4 + h4], a, bfr[h4],
                                           cw.x, cw.y);
                            } else {
                                mma16816(acc[jf*8 + hh*4 + h4], a, bfr[h4]);
                            }
                        }
                    }
                }
            }

            // ---- epilogue: relu*wd dot (2-way chains), quad reduce, store ----
            const int ig2 = ibase + ii;
            float2 wdw[8];
            #pragma unroll
            for (int ht = 0; ht < 8; ht++)
                wdw[ht] = *reinterpret_cast<const float2*>(&wds[ht*8 + t2]);
            float p[4];
            #pragma unroll
            for (int jf = 0; jf < 2; jf++) {
                float s0a = 0.f, s0b = 0.f, s1a = 0.f, s1b = 0.f;
                #pragma unroll
                for (int ht = 0; ht < 4; ht++) {
                    s0a += fmaxf(acc[jf*8+ht][0], 0.f) * wdw[ht].x
                         + fmaxf(acc[jf*8+ht][1], 0.f) * wdw[ht].y;
                    s1a += fmaxf(acc[jf*8+ht][2], 0.f) * wdw[ht].x
                         + fmaxf(acc[jf*8+ht][3], 0.f) * wdw[ht].y;
                    s0b += fmaxf(acc[jf*8+4+ht][0], 0.f) * wdw[4+ht].x
                         + fmaxf(acc[jf*8+4+ht][1], 0.f) * wdw[4+ht].y;
                    s1b += fmaxf(acc[jf*8+4+ht][2], 0.f) * wdw[4+ht].x
                         + fmaxf(acc[jf*8+4+ht][3], 0.f) * wdw[4+ht].y;
                }
                float s0 = s0a + s0b;
                float s1 = s1a + s1b;
                s0 += __shfl_xor_sync(0xffffffffu, s0, 1);
                s0 += __shfl_xor_sync(0xffffffffu, s0, 2);
                s1 += __shfl_xor_sync(0xffffffffu, s1, 1);
                s1 += __shfl_xor_sync(0xffffffffu, s1, 2);
                p[jf*2 + 0] = s0;
                p[jf*2 + 1] = s1;
            }
            const int g   = lane & 7;
            const int src = g * 4;
            float v0 = __shfl_sync(0xffffffffu, p[0], src);
            float v1 = __shfl_sync(0xffffffffu, p[1], src);
            float v2 = __shfl_sync(0xffffffffu, p[2], src);
            float v3 = __shfl_sync(0xffffffffu, p[3], src);
            const int q2 = lane >> 3;
            float d = (q2 == 0) ? v0 : (q2 == 1) ? v1 : (q2 == 2) ? v2 : v3;
            d += bd;
            const int j = wj + ((lane >> 4) << 4) + (((lane >> 3) & 1) << 3) + g;
            store_edge(out, b, ig2, j, d);
        }
        if (phase == 0) __syncthreads();
    }

    // ================= barrier reset (replay-deterministic) ===============
    __syncthreads();
    if (t == 0) {
        int v = atomicAdd(&g_cout, 1);
        if (v == 127) {
            atomicExch(&g_cin, 0);
            atomicExch(&g_cout, 0);
        }
    }
}

// =====================================================================
extern "C" void kernel_launch(void* const* d_in, const int* in_sizes, int n_in,
                              void* d_out, int out_size)
{
    (void)in_sizes; (void)n_in; (void)out_size;
    const float* nf   = (const float*)d_in[0];
    const float* fc1w = (const float*)d_in[1];
    const float* fc1b = (const float*)d_in[2];
    const float* fc2w = (const float*)d_in[3];
    const float* fc2b = (const float*)d_in[4];
    const float* e1w  = (const float*)d_in[5];
    const float* e1b  = (const float*)d_in[6];
    const float* e2w  = (const float*)d_in[7];
    const float* e2b  = (const float*)d_in[8];
    float* out = (float*)d_out;

    cudaFuncSetAttribute(fused, cudaFuncAttributeMaxDynamicSharedMemorySize, SM2_TOTAL);
    fused<<<128, 512, SM2_TOTAL>>>(nf, fc1w, fc1b, fc2w, fc2b,
                                   e1w, e1b, e2w, e2b, out);
}